// round 12
// baseline (speedup 1.0000x reference)
#include <cuda_runtime.h>
#include <cstdint>

#define NB 8
#define NC 256
#define NQ 4096
#define NK 4096
#define KNN 8
#define KCHUNK 2048
#define FULLM 0xffffffffu

// Scratch (static __device__ globals — allocation-free per harness rules)
__device__ float g_KT[(size_t)NB * NK * NC];   // key_features transposed (B,NK,C)
__device__ int   g_idx[(size_t)NB * NQ * KNN]; // knn indices

#define QPB 32                                  // queries per knn block (8 warps x 4)
#define KNN_BLOCKS (NB * (NQ / QPB))            // 1024
#define TR_BLOCKS  (NB * (NK / 32) * (NC / 32)) // 8192
#define PREP_BLOCKS (KNN_BLOCKS + TR_BLOCKS)

#define GATHER_BLOCKS 2048                      // diff-half gather blocks
#define BC_BLOCKS  8192                         // broadcast-half writer blocks
#define OUT_BLOCKS (GATHER_BLOCKS + BC_BLOCKS)
#define BC_THREADS ((size_t)BC_BLOCKS * 256)

// ---- packed f32x2 helpers (sm_103a); each half rounds exactly like the
// ---- corresponding scalar __fmul_rn/__fadd_rn/__fmaf_rn ----
#define MUL2(o, a, b)    asm("mul.rn.f32x2 %0, %1, %2;"     : "=l"(o) : "l"(a), "l"(b))
#define ADD2(o, a, b)    asm("add.rn.f32x2 %0, %1, %2;"     : "=l"(o) : "l"(a), "l"(b))
#define FMA2(o, a, b, c) asm("fma.rn.f32x2 %0, %1, %2, %3;" : "=l"(o) : "l"(a), "l"(b), "l"(c))
#define PACK2(o, lo, hi) asm("mov.b64 %0, {%1, %2};" : "=l"(o) : "f"(lo), "f"(hi))
#define UNPACK2(lo, hi, v) asm("mov.b64 {%0, %1}, %2;" : "=f"(lo), "=f"(hi) : "l"(v))

// ---------------------------------------------------------------------------
// Prep kernel, two sequential block ranges:
//  [0, KNN_BLOCKS)   warp-cooperative kNN (4 queries per warp)
//  [+, +TR_BLOCKS)   transpose key_features (B,C,NK) -> g_KT (B,NK,C)
// (The broadcast output half moved to the gather launch — it has no
//  dependency on g_idx/g_KT and the gather kernel has DRAM headroom.)
//
// kNN semantics (bit-exact vs XLA reference):
//   qq  = rn(rn(rn(x*x)+rn(y*y))+rn(z*z))           (no fma)
//   dot = fma(qz,kz, fma(qy,ky, rn(qx*kx)))         (GEMM k-ascending chain)
//   d   = rn(rn(qq - 2*dot) + kk)                   (fma(dot,-2,qq) identical:
//                                                    -2*dot is exact)
// Ascending key order + strict '<' entry + strictly-greater shift
// => identical tie behavior to jax.lax.top_k.
// ---------------------------------------------------------------------------
__global__ void prep_kernel(const float* __restrict__ qc,
                            const float* __restrict__ kc,
                            const float* __restrict__ kf) {
    __shared__ __align__(16) unsigned char smem_raw[KCHUNK * 16]; // 32KB
    int tid = threadIdx.x;  // 256

    if (blockIdx.x >= KNN_BLOCKS) {
        // ---------------- transpose (B,C,NK) -> (B,NK,C) ----------------
        float (*t)[33] = reinterpret_cast<float (*)[33]>(smem_raw);
        int idx = blockIdx.x - KNN_BLOCKS;
        int b   = idx >> 10;
        int rem = idx & 1023;
        int n0  = (rem & 127) * 32;
        int c0  = (rem >> 7) * 32;
        int tx = tid & 31, ty0 = tid >> 5;
#pragma unroll
        for (int dy = 0; dy < 32; dy += 8) {
            int ty = ty0 + dy;
            t[ty][tx] = kf[((size_t)b * NC + c0 + ty) * NK + n0 + tx];
        }
        __syncthreads();
#pragma unroll
        for (int dy = 0; dy < 32; dy += 8) {
            int ty = ty0 + dy;
            g_KT[((size_t)b * NK + n0 + ty) * NC + c0 + tx] = t[tx][ty];
        }
        return;
    }

    // ----------------------------- kNN ----------------------------------
    float4* sk = reinterpret_cast<float4*>(smem_raw);  // KCHUNK float4
    int bid  = blockIdx.x;
    int b    = bid >> 7;          // / (NQ/QPB = 128)
    int qblk = bid & 127;
    int wid  = tid >> 5, lane = tid & 31;
    int n0q = qblk * QPB + wid * 4;   // queries n0q .. n0q+3

    const float* kb = kc + (size_t)b * 3 * NK;
    const float* qb = qc + (size_t)b * 3 * NQ;

    float qx[4], qy[4], qz[4], qq[4];
#pragma unroll
    for (int q = 0; q < 4; q++) {
        int n = n0q + q;
        qx[q] = qb[n]; qy[q] = qb[NQ + n]; qz[q] = qb[2 * NQ + n];
        qq[q] = __fadd_rn(__fadd_rn(__fmul_rn(qx[q], qx[q]),
                                    __fmul_rn(qy[q], qy[q])),
                          __fmul_rn(qz[q], qz[q]));
    }
    unsigned long long qxAB, qyAB, qzAB, qqAB, qxCD, qyCD, qzCD, qqCD, m2;
    PACK2(qxAB, qx[0], qx[1]); PACK2(qyAB, qy[0], qy[1]);
    PACK2(qzAB, qz[0], qz[1]); PACK2(qqAB, qq[0], qq[1]);
    PACK2(qxCD, qx[2], qx[3]); PACK2(qyCD, qy[2], qy[3]);
    PACK2(qzCD, qz[2], qz[3]); PACK2(qqCD, qq[2], qq[3]);
    PACK2(m2, -2.0f, -2.0f);

    float bd = 3.4e38f;   // lane segment s holds query s's sorted top-8
    int   bi = 0;
    float thrA = 3.4e38f, thrB = 3.4e38f, thrC = 3.4e38f, thrD = 3.4e38f;

#define PROCESS(D, THR, LLO, LHI)                                             \
    do {                                                                      \
        unsigned bal = __ballot_sync(FULLM, (D) < (THR));                     \
        while (bal) {                   /* warp-uniform candidate loop */     \
            int j = __ffs(bal) - 1; bal &= bal - 1;                           \
            float dj = __shfl_sync(FULLM, (D), j);                            \
            if (dj < (THR)) {                                                 \
                float bp = __shfl_up_sync(FULLM, bd, 1);                      \
                int   ip = __shfl_up_sync(FULLM, bi, 1);                      \
                if (lane >= (LLO) && lane < (LHI) && bd > dj) {               \
                    bool tp = (lane > (LLO)) && (bp > dj);                    \
                    bd = tp ? bp : dj;                                        \
                    bi = tp ? ip : (base + j);                                \
                }                                                             \
                (THR) = __shfl_sync(FULLM, bd, (LHI) - 1);                    \
            }                                                                 \
        }                                                                     \
    } while (0)

    for (int m0 = 0; m0 < NK; m0 += KCHUNK) {
        __syncthreads();
        for (int m = tid; m < KCHUNK; m += 256) {
            float x = kb[m0 + m];
            float y = kb[NK + m0 + m];
            float z = kb[2 * NK + m0 + m];
            float kk = __fadd_rn(__fadd_rn(__fmul_rn(x, x), __fmul_rn(y, y)),
                                 __fmul_rn(z, z));
            sk[m] = make_float4(x, y, z, kk);
        }
        __syncthreads();

        for (int it = 0; it < KCHUNK / 32; it++) {
            float4 k4 = sk[it * 32 + lane];
            unsigned long long kx2, ky2, kz2, kk2, dot2, t2, d2;
            PACK2(kx2, k4.x, k4.x); PACK2(ky2, k4.y, k4.y);
            PACK2(kz2, k4.z, k4.z); PACK2(kk2, k4.w, k4.w);
            // queries A,B (halves bit-identical to scalar XLA chain)
            MUL2(dot2, qxAB, kx2);
            FMA2(dot2, qyAB, ky2, dot2);
            FMA2(dot2, qzAB, kz2, dot2);
            FMA2(t2, dot2, m2, qqAB);      // rn(qq - 2*dot)
            ADD2(d2, t2, kk2);
            float dA, dB;
            UNPACK2(dA, dB, d2);
            // queries C,D
            MUL2(dot2, qxCD, kx2);
            FMA2(dot2, qyCD, ky2, dot2);
            FMA2(dot2, qzCD, kz2, dot2);
            FMA2(t2, dot2, m2, qqCD);
            ADD2(d2, t2, kk2);
            float dC, dD;
            UNPACK2(dC, dD, d2);

            int base = m0 + it * 32;
            PROCESS(dA, thrA, 0, 8);
            PROCESS(dB, thrB, 8, 16);
            PROCESS(dC, thrC, 16, 24);
            PROCESS(dD, thrD, 24, 32);
        }
    }
#undef PROCESS

    // lanes [8q, 8q+8) hold query (n0q+q)'s sorted indices
    int* o = g_idx + ((size_t)b * NQ + n0q) * KNN;
    o[(lane >> 3) * KNN + (lane & 7)] = bi;
}

// ---------------------------------------------------------------------------
// Output kernel, two block ranges (both DRAM-bound, share the launch):
//  [0, GATHER_BLOCKS)  diff half: out[b][c][n][k] = KT[b][idx[n][k]][c]-qf[b][c][n]
//  [+, +BC_BLOCKS)     broadcast half: out[b][256+c][n][k] = qf[b][c][n]
// ---------------------------------------------------------------------------
#define NT 16
#define NP (NT * KNN)
#define CCH 64

__global__ void out_kernel(const float* __restrict__ qf,
                           float* __restrict__ out) {
    __shared__ __align__(16) float S[CCH * 128];   // 32KB, swizzled
    __shared__ float Qs[NT][CCH + 1];
    __shared__ int   sidx[NP];

    int tid = threadIdx.x;  // 256

    if (blockIdx.x >= GATHER_BLOCKS) {
        // ------------- broadcast half: pure coalesced streaming write -----
        float4* out4 = reinterpret_cast<float4*>(out);
        size_t t0 = ((size_t)(blockIdx.x - GATHER_BLOCKS) * 256 + tid);
#pragma unroll
        for (int j = 0; j < 8; j++) {
            size_t G = t0 + (size_t)j * BC_THREADS;  // [0, 16M)
            int n = (int)((G >> 1) & (NQ - 1));
            int c = (int)((G >> 13) & (NC - 1));
            int b = (int)(G >> 21);
            float q = qf[((size_t)b * NC + c) * NQ + n];
            __stcs(&out4[G + ((size_t)b + 1) * 2097152],
                   make_float4(q, q, q, q));
        }
        return;
    }

    // ----------------- diff-half gather (proven 87.7us path) -------------
    int b   = blockIdx.x >> 8;
    int n0  = (blockIdx.x & 255) * NT;

    if (tid < NP) sidx[tid] = g_idx[((size_t)b * NQ + n0) * KNN + tid];
    __syncthreads();

    const float* KTb = g_KT + (size_t)b * NK * NC;

    for (int c0 = 0; c0 < NC; c0 += CCH) {
        if (c0) __syncthreads();

        // Phase 1: gather KT rows. 16 lanes per pair -> 256B contiguous reads.
#pragma unroll
        for (int i = tid; i < NP * (CCH / 4); i += 256) {
            int p  = i >> 4;          // pair [0,128)
            int c4 = (i & 15) * 4;    // channel quad base [0,64)
            float4 v = *reinterpret_cast<const float4*>(
                &KTb[(size_t)sidx[p] * NC + c0 + c4]);
            int col = p ^ c4;         // swizzle
            S[(c4 + 0) * 128 + col] = v.x;
            S[(c4 + 1) * 128 + col] = v.y;
            S[(c4 + 2) * 128 + col] = v.z;
            S[(c4 + 3) * 128 + col] = v.w;
        }
#pragma unroll
        for (int i = tid; i < NT * CCH; i += 256) {
            int c = i >> 4, j = i & 15;
            Qs[j][c] = qf[((size_t)b * NC + c0 + c) * NQ + n0 + j];
        }
        __syncthreads();

        // Phase 3: conflict-free LDS.128, coalesced float4 streaming stores.
#pragma unroll
        for (int i = tid; i < CCH * (NP / 4); i += 256) {
            int c = i >> 5;            // row [0,64)
            int l = i & 31;            // quad index; p = 4*l
            float4 v = *reinterpret_cast<const float4*>(
                &S[c * 128 + ((4 * l) ^ (c & 0x7C))]);
            float q = Qs[l >> 1][c];   // p>>3 = l>>1
            float4 d;
            d.x = v.x - q;
            d.y = v.y - q;
            d.z = v.z - q;
            d.w = v.w - q;
            size_t ob = (((size_t)b * (2 * NC) + c0 + c) * NQ + n0) * KNN + 4 * l;
            __stcs(reinterpret_cast<float4*>(&out[ob]), d);
        }
    }
}

// ---------------------------------------------------------------------------
extern "C" void kernel_launch(void* const* d_in, const int* in_sizes, int n_in,
                              void* d_out, int out_size) {
    const float* query_coords   = (const float*)d_in[0]; // (B,3,NQ)
    const float* query_features = (const float*)d_in[1]; // (B,C,NQ)
    const float* key_coords     = (const float*)d_in[2]; // (B,3,NK)
    const float* key_features   = (const float*)d_in[3]; // (B,C,NK)
    float* out = (float*)d_out;                          // (B,2C,NQ,K)

    prep_kernel<<<PREP_BLOCKS, 256>>>(query_coords, key_coords, key_features);
    out_kernel<<<OUT_BLOCKS, 256>>>(query_features, out);
}

// round 13
// speedup vs baseline: 1.1380x; 1.1380x over previous
#include <cuda_runtime.h>
#include <cstdint>

#define NB 8
#define NC 256
#define NQ 4096
#define NK 4096
#define KNN 8
#define KCHUNK 2048
#define FULLM 0xffffffffu

// Scratch (static __device__ globals — allocation-free per harness rules)
__device__ float g_KT[(size_t)NB * NK * NC];   // key_features transposed (B,NK,C)
__device__ int   g_idx[(size_t)NB * NQ * KNN]; // knn indices

#define QPB 32                                  // queries per knn block (8 warps x 4)
#define KNN_BLOCKS (NB * (NQ / QPB))            // 1024
#define BC_BLOCKS  8192                         // broadcast-half writer blocks
#define TR_BLOCKS  (NB * (NK / 32) * (NC / 32)) // 8192
#define BC_THREADS ((size_t)BC_BLOCKS * 256)

// ---- packed f32x2 helpers (sm_103a); each half rounds exactly like the
// ---- corresponding scalar __fmul_rn/__fadd_rn/__fmaf_rn ----
#define MUL2(o, a, b)    asm("mul.rn.f32x2 %0, %1, %2;"     : "=l"(o) : "l"(a), "l"(b))
#define ADD2(o, a, b)    asm("add.rn.f32x2 %0, %1, %2;"     : "=l"(o) : "l"(a), "l"(b))
#define FMA2(o, a, b, c) asm("fma.rn.f32x2 %0, %1, %2, %3;" : "=l"(o) : "l"(a), "l"(b), "l"(c))
#define PACK2(o, lo, hi) asm("mov.b64 %0, {%1, %2};" : "=l"(o) : "f"(lo), "f"(hi))
#define UNPACK2(lo, hi, v) asm("mov.b64 {%0, %1}, %2;" : "=f"(lo), "=f"(hi) : "l"(v))

// ---------------------------------------------------------------------------
// Fused prep kernel, three sequential block ranges (R11 champion structure):
//  [0, KNN_BLOCKS)        warp-cooperative kNN (4 queries per warp)
//  [+, +BC_BLOCKS)        broadcast half: out[b][256+c][n][k] = qf[b][c][n]
//  [+, +TR_BLOCKS)        transpose key_features (B,C,NK) -> g_KT (B,NK,C)
//
// kNN semantics (bit-exact vs XLA reference):
//   qq  = rn(rn(rn(x*x)+rn(y*y))+rn(z*z))           (no fma)
//   dot = fma(qz,kz, fma(qy,ky, rn(qx*kx)))         (GEMM k-ascending chain)
//   d   = rn(rn(qq - 2*dot) + kk)                   (fma(dot,-2,qq) identical:
//                                                    -2*dot is exact)
// Ascending key order + strict '<' entry + strictly-greater shift
// => identical tie behavior to jax.lax.top_k.
// Four sorted top-8 lists in lane segments 0-7/8-15/16-23/24-31.
// NEW (R13): one combined prefilter ballot skips all four candidate loops
// in the ~64% of iterations with no candidate for any query.
// ---------------------------------------------------------------------------
__global__ void prep_kernel(const float* __restrict__ qc,
                            const float* __restrict__ kc,
                            const float* __restrict__ kf,
                            const float* __restrict__ qf,
                            float* __restrict__ out) {
    __shared__ __align__(16) unsigned char smem_raw[KCHUNK * 16]; // 32KB
    int tid = threadIdx.x;  // 256

    if (blockIdx.x >= KNN_BLOCKS && blockIdx.x < KNN_BLOCKS + BC_BLOCKS) {
        // ------------- broadcast half: pure coalesced streaming write -----
        float4* out4 = reinterpret_cast<float4*>(out);
        size_t t0 = ((size_t)(blockIdx.x - KNN_BLOCKS) * 256 + tid);
#pragma unroll
        for (int j = 0; j < 8; j++) {
            size_t G = t0 + (size_t)j * BC_THREADS;  // [0, 16M)
            int n = (int)((G >> 1) & (NQ - 1));
            int c = (int)((G >> 13) & (NC - 1));
            int b = (int)(G >> 21);
            float q = qf[((size_t)b * NC + c) * NQ + n];
            float4 v = make_float4(q, q, q, q);
            __stcs(&out4[G + ((size_t)b + 1) * 2097152], v);
        }
        return;
    }

    if (blockIdx.x >= KNN_BLOCKS + BC_BLOCKS) {
        // ---------------- transpose (B,C,NK) -> (B,NK,C) ----------------
        float (*t)[33] = reinterpret_cast<float (*)[33]>(smem_raw);
        int idx = blockIdx.x - KNN_BLOCKS - BC_BLOCKS;
        int b   = idx >> 10;
        int rem = idx & 1023;
        int n0  = (rem & 127) * 32;
        int c0  = (rem >> 7) * 32;
        int tx = tid & 31, ty0 = tid >> 5;
#pragma unroll
        for (int dy = 0; dy < 32; dy += 8) {
            int ty = ty0 + dy;
            t[ty][tx] = kf[((size_t)b * NC + c0 + ty) * NK + n0 + tx];
        }
        __syncthreads();
#pragma unroll
        for (int dy = 0; dy < 32; dy += 8) {
            int ty = ty0 + dy;
            g_KT[((size_t)b * NK + n0 + ty) * NC + c0 + tx] = t[tx][ty];
        }
        return;
    }

    // ----------------------------- kNN ----------------------------------
    float4* sk = reinterpret_cast<float4*>(smem_raw);  // KCHUNK float4
    int bid  = blockIdx.x;
    int b    = bid >> 7;          // / (NQ/QPB = 128)
    int qblk = bid & 127;
    int wid  = tid >> 5, lane = tid & 31;
    int n0q = qblk * QPB + wid * 4;   // queries n0q .. n0q+3

    const float* kb = kc + (size_t)b * 3 * NK;
    const float* qb = qc + (size_t)b * 3 * NQ;

    float qx[4], qy[4], qz[4], qq[4];
#pragma unroll
    for (int q = 0; q < 4; q++) {
        int n = n0q + q;
        qx[q] = qb[n]; qy[q] = qb[NQ + n]; qz[q] = qb[2 * NQ + n];
        qq[q] = __fadd_rn(__fadd_rn(__fmul_rn(qx[q], qx[q]),
                                    __fmul_rn(qy[q], qy[q])),
                          __fmul_rn(qz[q], qz[q]));
    }
    unsigned long long qxAB, qyAB, qzAB, qqAB, qxCD, qyCD, qzCD, qqCD, m2;
    PACK2(qxAB, qx[0], qx[1]); PACK2(qyAB, qy[0], qy[1]);
    PACK2(qzAB, qz[0], qz[1]); PACK2(qqAB, qq[0], qq[1]);
    PACK2(qxCD, qx[2], qx[3]); PACK2(qyCD, qy[2], qy[3]);
    PACK2(qzCD, qz[2], qz[3]); PACK2(qqCD, qq[2], qq[3]);
    PACK2(m2, -2.0f, -2.0f);

    float bd = 3.4e38f;   // lane segment s holds query s's sorted top-8
    int   bi = 0;
    float thrA = 3.4e38f, thrB = 3.4e38f, thrC = 3.4e38f, thrD = 3.4e38f;

#define PROCESS(D, THR, LLO, LHI)                                             \
    do {                                                                      \
        unsigned bal = __ballot_sync(FULLM, (D) < (THR));                     \
        while (bal) {                   /* warp-uniform candidate loop */     \
            int j = __ffs(bal) - 1; bal &= bal - 1;                           \
            float dj = __shfl_sync(FULLM, (D), j);                            \
            if (dj < (THR)) {                                                 \
                float bp = __shfl_up_sync(FULLM, bd, 1);                      \
                int   ip = __shfl_up_sync(FULLM, bi, 1);                      \
                if (lane >= (LLO) && lane < (LHI) && bd > dj) {               \
                    bool tp = (lane > (LLO)) && (bp > dj);                    \
                    bd = tp ? bp : dj;                                        \
                    bi = tp ? ip : (base + j);                                \
                }                                                             \
                (THR) = __shfl_sync(FULLM, bd, (LHI) - 1);                    \
            }                                                                 \
        }                                                                     \
    } while (0)

    for (int m0 = 0; m0 < NK; m0 += KCHUNK) {
        __syncthreads();
        for (int m = tid; m < KCHUNK; m += 256) {
            float x = kb[m0 + m];
            float y = kb[NK + m0 + m];
            float z = kb[2 * NK + m0 + m];
            float kk = __fadd_rn(__fadd_rn(__fmul_rn(x, x), __fmul_rn(y, y)),
                                 __fmul_rn(z, z));
            sk[m] = make_float4(x, y, z, kk);
        }
        __syncthreads();

        for (int it = 0; it < KCHUNK / 32; it++) {
            float4 k4 = sk[it * 32 + lane];
            unsigned long long kx2, ky2, kz2, kk2, dot2, t2, d2;
            PACK2(kx2, k4.x, k4.x); PACK2(ky2, k4.y, k4.y);
            PACK2(kz2, k4.z, k4.z); PACK2(kk2, k4.w, k4.w);
            // queries A,B (halves bit-identical to scalar XLA chain)
            MUL2(dot2, qxAB, kx2);
            FMA2(dot2, qyAB, ky2, dot2);
            FMA2(dot2, qzAB, kz2, dot2);
            FMA2(t2, dot2, m2, qqAB);      // rn(qq - 2*dot)
            ADD2(d2, t2, kk2);
            float dA, dB;
            UNPACK2(dA, dB, d2);
            // queries C,D
            MUL2(dot2, qxCD, kx2);
            FMA2(dot2, qyCD, ky2, dot2);
            FMA2(dot2, qzCD, kz2, dot2);
            FMA2(t2, dot2, m2, qqCD);
            ADD2(d2, t2, kk2);
            float dC, dD;
            UNPACK2(dC, dD, d2);

            // R13: combined prefilter — skip all candidate loops when no
            // lane has a candidate for any of the 4 queries (~64% of iters).
            unsigned any = __ballot_sync(FULLM,
                (dA < thrA) | (dB < thrB) | (dC < thrC) | (dD < thrD));
            if (any) {
                int base = m0 + it * 32;
                PROCESS(dA, thrA, 0, 8);
                PROCESS(dB, thrB, 8, 16);
                PROCESS(dC, thrC, 16, 24);
                PROCESS(dD, thrD, 24, 32);
            }
        }
    }
#undef PROCESS

    // lanes [8q, 8q+8) hold query (n0q+q)'s sorted indices
    int* o = g_idx + ((size_t)b * NQ + n0q) * KNN;
    o[(lane >> 3) * KNN + (lane & 7)] = bi;
}

// ---------------------------------------------------------------------------
// Gather kernel: diff half only (byte-identical to R11's 87.7us version).
// out[b][c][n][k] = KT[b][idx[n][k]][c] - qf[b][c][n],  c in [0,256)
// S layout: row stride 128 floats, column = p ^ (row & ~3)  (XOR swizzle).
//  - phase 1: scalar STS, 2-way conflicts
//  - phase 3: ONE LDS.128 per quad, conflict-free
// ---------------------------------------------------------------------------
#define NT 16
#define NP (NT * KNN)
#define CCH 64

__global__ void gather_kernel(const float* __restrict__ qf,
                              float* __restrict__ out) {
    __shared__ __align__(16) float S[CCH * 128];   // 32KB, swizzled
    __shared__ float Qs[NT][CCH + 1];
    __shared__ int   sidx[NP];

    int b   = blockIdx.y;
    int n0  = blockIdx.x * NT;
    int tid = threadIdx.x;  // 256

    if (tid < NP) sidx[tid] = g_idx[((size_t)b * NQ + n0) * KNN + tid];
    __syncthreads();

    const float* KTb = g_KT + (size_t)b * NK * NC;

    for (int c0 = 0; c0 < NC; c0 += CCH) {
        if (c0) __syncthreads();

        // Phase 1: gather KT rows. 16 lanes per pair -> 256B contiguous reads.
#pragma unroll
        for (int i = tid; i < NP * (CCH / 4); i += 256) {
            int p  = i >> 4;          // pair [0,128)
            int c4 = (i & 15) * 4;    // channel quad base [0,64)
            float4 v = *reinterpret_cast<const float4*>(
                &KTb[(size_t)sidx[p] * NC + c0 + c4]);
            int col = p ^ c4;         // swizzle
            S[(c4 + 0) * 128 + col] = v.x;
            S[(c4 + 1) * 128 + col] = v.y;
            S[(c4 + 2) * 128 + col] = v.z;
            S[(c4 + 3) * 128 + col] = v.w;
        }
#pragma unroll
        for (int i = tid; i < NT * CCH; i += 256) {
            int c = i >> 4, j = i & 15;
            Qs[j][c] = qf[((size_t)b * NC + c0 + c) * NQ + n0 + j];
        }
        __syncthreads();

        // Phase 3: conflict-free LDS.128, coalesced float4 streaming stores.
#pragma unroll
        for (int i = tid; i < CCH * (NP / 4); i += 256) {
            int c = i >> 5;            // row [0,64)
            int l = i & 31;            // quad index; p = 4*l
            float4 v = *reinterpret_cast<const float4*>(
                &S[c * 128 + ((4 * l) ^ (c & 0x7C))]);
            float q = Qs[l >> 1][c];   // p>>3 = l>>1
            float4 d;
            d.x = v.x - q;
            d.y = v.y - q;
            d.z = v.z - q;
            d.w = v.w - q;
            size_t ob = (((size_t)b * (2 * NC) + c0 + c) * NQ + n0) * KNN + 4 * l;
            __stcs(reinterpret_cast<float4*>(&out[ob]), d);
        }
    }
}

// ---------------------------------------------------------------------------
extern "C" void kernel_launch(void* const* d_in, const int* in_sizes, int n_in,
                              void* d_out, int out_size) {
    const float* query_coords   = (const float*)d_in[0]; // (B,3,NQ)
    const float* query_features = (const float*)d_in[1]; // (B,C,NQ)
    const float* key_coords     = (const float*)d_in[2]; // (B,3,NK)
    const float* key_features   = (const float*)d_in[3]; // (B,C,NK)
    float* out = (float*)d_out;                          // (B,2C,NQ,K)

    prep_kernel<<<KNN_BLOCKS + BC_BLOCKS + TR_BLOCKS, 256>>>(
        query_coords, key_coords, key_features, query_features, out);
    {
        dim3 grid(NQ / NT, NB);
        gather_kernel<<<grid, 256>>>(query_features, out);
    }
}